// round 12
// baseline (speedup 1.0000x reference)
#include <cuda_runtime.h>

// GraphConvDown: per-edge MLP (35 -> 64 -> 64) + scatter-max onto M sampled points.
// Round 12: register-slimmed schedule (layer1 kf-outer with persistent accumulator
// bank that morphs into the layer-2 A bank; peak live regs ~60 vs 80) allowing
// TILE=160 / 320-thread blocks at 3 blocks/SM -> 30 warps (occ 47% vs 35%).
// Math identical to R9-R11 (bf16 m16n8k16, 3-term split), rel_err 4.12e-6.
//
// Output layout (float32): out[0..4M) = new_bxyz [M,4]; out[4M..4M+64M) = new_feat [M,64]

#define K1 35
#define MAXM 131072
#define MAXE 2000128
#define SCAN_BLK 1024
#define TILE 160
#define TPB 8
#define THREADS 320

// ---------- static scratch ----------
__device__ int      g_cnt[MAXM];
__device__ int      g_start[MAXM];
__device__ int      g_cursor[MAXM];
__device__ unsigned g_state[128];
__device__ int2     g_sorted[MAXE];
__device__ uint2    g_W1i[24 * 64];    // (hi, lo) bf16x2 pairs, k padded 35->48
__device__ uint2    g_W2i[32 * 64];    // k=64

__device__ __forceinline__ unsigned pack_bf16(float x, float y) {
    unsigned r;
    asm("cvt.rn.bf16x2.f32 %0, %1, %2;" : "=r"(r) : "f"(y), "f"(x));
    return r;
}
__device__ __forceinline__ void split_pair(float x, float y, unsigned& hi, unsigned& lo) {
    hi = pack_bf16(x, y);
    float hx = __uint_as_float(hi << 16);
    float hy = __uint_as_float(hi & 0xffff0000u);
    lo = pack_bf16(x - hx, y - hy);
}

// ---------------------------------------------------------------------------
// 1) init + weight split + histogram
// ---------------------------------------------------------------------------
__global__ void k_init_hist(const float4* __restrict__ bxyz4,
                            const int* __restrict__ sample_idx,
                            const int* __restrict__ e_new,
                            const float* __restrict__ W1,
                            const float* __restrict__ W2,
                            float* __restrict__ out, int M, int E) {
    int i = blockIdx.x * blockDim.x + threadIdx.x;
    int stride = gridDim.x * blockDim.x;
    float4* ob = (float4*)out;
    for (int j = i; j < M; j += stride)
        ob[j] = bxyz4[sample_idx[j]];
    float4* fz = (float4*)(out + 4 * (size_t)M);
    int tot = M * 16;
    for (int j = i; j < tot; j += stride)
        fz[j] = make_float4(0.f, 0.f, 0.f, 0.f);
    for (int j = i; j < 24 * 64; j += stride) {
        int kp = j >> 6, n = j & 63;
        int k0 = 2 * kp, k1 = 2 * kp + 1;
        float w0 = (k0 < K1) ? W1[k0 * 64 + n] : 0.f;
        float w1 = (k1 < K1) ? W1[k1 * 64 + n] : 0.f;
        unsigned hi, lo;
        split_pair(w0, w1, hi, lo);
        g_W1i[j] = make_uint2(hi, lo);
    }
    for (int j = i; j < 32 * 64; j += stride) {
        int kp = j >> 6, n = j & 63;
        float w0 = W2[(2 * kp) * 64 + n];
        float w1 = W2[(2 * kp + 1) * 64 + n];
        unsigned hi, lo;
        split_pair(w0, w1, hi, lo);
        g_W2i[j] = make_uint2(hi, lo);
    }
    for (int j = i; j < E; j += stride)
        atomicAdd(&g_cnt[e_new[j]], 1);
}

// ---------------------------------------------------------------------------
// 2) decoupled-lookback exclusive scan (123 blocks, single wave)
// ---------------------------------------------------------------------------
__global__ void k_scan(int M) {
    __shared__ int sh[SCAN_BLK];
    __shared__ int s_prefix;
    int bid = blockIdx.x;
    int tid = threadIdx.x;
    int i = bid * SCAN_BLK + tid;
    int c = (i < M) ? g_cnt[i] : 0;
    sh[tid] = c;
    __syncthreads();
    for (int d = 1; d < SCAN_BLK; d <<= 1) {
        int t = (tid >= d) ? sh[tid - d] : 0;
        __syncthreads();
        sh[tid] += t;
        __syncthreads();
    }
    int incl = sh[tid];
    if (tid == 0) {
        unsigned agg = (unsigned)sh[SCAN_BLK - 1];
        if (bid == 0) {
            atomicExch(&g_state[0], (2u << 30) | agg);
            s_prefix = 0;
        } else {
            atomicExch(&g_state[bid], (1u << 30) | agg);
            unsigned run = 0;
            int j = bid - 1;
            while (true) {
                unsigned s;
                do { s = atomicAdd(&g_state[j], 0u); } while ((s >> 30) == 0u);
                run += s & 0x3fffffffu;
                if ((s >> 30) == 2u) break;
                j--;
            }
            atomicExch(&g_state[bid], (2u << 30) | (run + agg));
            s_prefix = (int)run;
        }
    }
    __syncthreads();
    if (i < M) g_start[i] = s_prefix + incl - c;
}

// ---------------------------------------------------------------------------
// 3) counting-sort scatter
// ---------------------------------------------------------------------------
__global__ void k_scatter(const int* __restrict__ e_point,
                          const int* __restrict__ e_new, int E) {
    int i = blockIdx.x * blockDim.x + threadIdx.x;
    if (i < E) {
        int m = e_new[i];
        int pos = g_start[m] + atomicAdd(&g_cursor[m], 1);
        g_sorted[pos] = make_int2(e_point[i], m);
    }
}

// ---------------------------------------------------------------------------
__device__ __forceinline__ void mma_bf16(float& c0, float& c1, float& c2, float& c3,
                                         unsigned a0, unsigned a1, unsigned a2, unsigned a3,
                                         unsigned b0, unsigned b1) {
    asm volatile("mma.sync.aligned.m16n8k16.row.col.f32.bf16.bf16.f32 "
                 "{%0,%1,%2,%3}, {%4,%5,%6,%7}, {%8,%9}, {%0,%1,%2,%3};"
                 : "+f"(c0), "+f"(c1), "+f"(c2), "+f"(c3)
                 : "r"(a0), "r"(a1), "r"(a2), "r"(a3), "r"(b0), "r"(b1));
}

// SMEM layout (32-bit word offsets).
#define S_W1   0                          // uint2 [24][68]
#define S_W2   (24 * 68)                  // uint2 [32][68]
#define W_TOT  (S_W2 + 32 * 68)           // 3808 uint2 = 7616 words
#define S_B1   (2 * W_TOT)
#define S_B2   (S_B1 + 64)
#define S_MM   (S_B2 + 64)                // [160] int
#define S_SC   (S_MM + 160)               // [160][68] f32
#define SMEM_WORDS (S_SC + 160 * 68)      // 18784 words = 75136 B -> 3 blocks/SM

// ---------------------------------------------------------------------------
// 4) main tensor-core kernel: 320 threads (10 warps), 160-edge tiles.
// ---------------------------------------------------------------------------
__global__ __launch_bounds__(THREADS, 3)
void k_main_tc(const float4* __restrict__ bxyz4,
               const float4* __restrict__ feat4,
               const float*  __restrict__ b1, const float* __restrict__ b2,
               const float4* __restrict__ newb4,
               int*          __restrict__ outf,
               int E, int M)
{
    extern __shared__ float sm[];
    uint2* W1s = (uint2*)sm + S_W1;
    uint2* W2s = (uint2*)sm + S_W2;
    float* b1s = sm + S_B1;
    float* b2s = sm + S_B2;
    int*   smm = (int*)(sm + S_MM);
    float* sc  = sm + S_SC;

    int tid  = threadIdx.x;
    int warp = tid >> 5;
    int lane = tid & 31;
    int g    = lane >> 2;
    int tg   = lane & 3;

    // ---- replay-state zeroing (grid*320 covers M) ----
    {
        int gt = blockIdx.x * THREADS + tid;
        if (gt < M) { g_cnt[gt] = 0; g_cursor[gt] = 0; }
        if (gt < 128) g_state[gt] = 0u;
    }

    // ---- stage weights (once per block, amortized over 10 warps) ----
    for (int i = tid; i < 24 * 64; i += THREADS) {
        int kp = i >> 6, n = i & 63;
        W1s[kp * 68 + n] = g_W1i[i];
    }
    for (int i = tid; i < 32 * 64; i += THREADS) {
        int kp = i >> 6, n = i & 63;
        W2s[kp * 68 + n] = g_W2i[i];
    }
    if (tid < 64) { b1s[tid] = b1[tid]; b2s[tid] = b2[tid]; }

    for (int tb = 0; tb < TPB; tb++) {
        int base = (blockIdx.x * TPB + tb) * TILE;
        if (base >= E) break;
        __syncthreads();    // prior epilogue done before sc/smm reuse

        // ---- stage 160 edge rows, 2 threads per row (warp-local rows) ----
        {
            int row  = tid >> 1;
            int half = tid & 1;
            int e = base + row;
            float* rp = sc + row * 68;
            if (e < E) {
                int2 em = g_sorted[e];
                int p = em.x, m = em.y;
                const float4* fp = feat4 + (size_t)p * 8;
                if (half == 0) {
                    smm[row] = m;
                    #pragma unroll
                    for (int q = 0; q < 4; q++) ((float4*)rp)[q] = fp[q];
                } else {
                    #pragma unroll
                    for (int q = 4; q < 8; q++) ((float4*)rp)[q] = fp[q];
                    float4 pb = bxyz4[p];
                    float4 nb = newb4[m];
                    ((float4*)rp)[8]  = make_float4(pb.y - nb.y, pb.z - nb.z, pb.w - nb.w, 0.f);
                    ((float4*)rp)[9]  = make_float4(0.f, 0.f, 0.f, 0.f);
                    ((float4*)rp)[10] = make_float4(0.f, 0.f, 0.f, 0.f);
                    ((float4*)rp)[11] = make_float4(0.f, 0.f, 0.f, 0.f);
                }
            } else {
                if (half == 0) {
                    smm[row] = -1;
                    #pragma unroll
                    for (int q = 0; q < 4; q++) ((float4*)rp)[q] = make_float4(0.f,0.f,0.f,0.f);
                } else {
                    #pragma unroll
                    for (int q = 4; q < 12; q++) ((float4*)rp)[q] = make_float4(0.f,0.f,0.f,0.f);
                }
            }
        }
        __syncwarp();       // staging rows and compute rows are warp-local

        int ra = warp * 16 + g;

        // ===== Layer 1, kf-outer with persistent accumulator bank (32 regs) =====
        float acc[8][4];
        #pragma unroll
        for (int nt = 0; nt < 8; nt++) {
            acc[nt][0] = 0.f; acc[nt][1] = 0.f; acc[nt][2] = 0.f; acc[nt][3] = 0.f;
        }
        #pragma unroll
        for (int kf = 0; kf < 3; kf++) {
            int k0 = kf * 16 + 2 * tg;
            float2 p0 = *(float2*)&sc[ra * 68 + k0];
            float2 p1 = *(float2*)&sc[(ra + 8) * 68 + k0];
            float2 p2 = *(float2*)&sc[ra * 68 + k0 + 8];
            float2 p3 = *(float2*)&sc[(ra + 8) * 68 + k0 + 8];
            unsigned ah0, ah1, ah2, ah3, al0, al1, al2, al3;
            split_pair(p0.x, p0.y, ah0, al0);
            split_pair(p1.x, p1.y, ah1, al1);
            split_pair(p2.x, p2.y, ah2, al2);
            split_pair(p3.x, p3.y, ah3, al3);
            #pragma unroll
            for (int nt = 0; nt < 8; nt++) {
                int nb = nt * 8 + g;
                uint2 w0 = W1s[(kf * 8 + tg) * 68 + nb];        // (bh0, bl0)
                uint2 w1 = W1s[(kf * 8 + tg + 4) * 68 + nb];    // (bh1, bl1)
                mma_bf16(acc[nt][0], acc[nt][1], acc[nt][2], acc[nt][3], ah0, ah1, ah2, ah3, w0.x, w1.x);
                mma_bf16(acc[nt][0], acc[nt][1], acc[nt][2], acc[nt][3], al0, al1, al2, al3, w0.x, w1.x);
                mma_bf16(acc[nt][0], acc[nt][1], acc[nt][2], acc[nt][3], ah0, ah1, ah2, ah3, w0.y, w1.y);
            }
        }

        // ---- bias + relu + split: acc bank morphs into layer-2 A bank (32 regs) ----
        unsigned a2h[4][4], a2l[4][4];
        #pragma unroll
        for (int nt = 0; nt < 8; nt++) {
            int col = nt * 8 + 2 * tg;
            float v0 = fmaxf(acc[nt][0] + b1s[col], 0.f);
            float v1 = fmaxf(acc[nt][1] + b1s[col + 1], 0.f);
            float v2 = fmaxf(acc[nt][2] + b1s[col], 0.f);
            float v3 = fmaxf(acc[nt][3] + b1s[col + 1], 0.f);
            // C-frag (rows g/g+8, cols 8nt+2tg) == layer-2 A-frag kf2=nt>>1
            int kf2 = nt >> 1;
            int ix  = (nt & 1) * 2;
            split_pair(v0, v1, a2h[kf2][ix],     a2l[kf2][ix]);
            split_pair(v2, v3, a2h[kf2][ix + 1], a2l[kf2][ix + 1]);
        }

        // ===== Layer 2, nt-outer (a2 bank live, one 4-reg accumulator) =====
        #pragma unroll
        for (int nt = 0; nt < 8; nt++) {
            float c0 = 0.f, c1 = 0.f, c2 = 0.f, c3 = 0.f;
            int nb = nt * 8 + g;
            #pragma unroll
            for (int kf = 0; kf < 4; kf++) {
                uint2 w0 = W2s[(kf * 8 + tg) * 68 + nb];
                uint2 w1 = W2s[(kf * 8 + tg + 4) * 68 + nb];
                mma_bf16(c0, c1, c2, c3, a2h[kf][0], a2h[kf][1], a2h[kf][2], a2h[kf][3], w0.x, w1.x);
                mma_bf16(c0, c1, c2, c3, a2l[kf][0], a2l[kf][1], a2l[kf][2], a2l[kf][3], w0.x, w1.x);
                mma_bf16(c0, c1, c2, c3, a2h[kf][0], a2h[kf][1], a2h[kf][2], a2h[kf][3], w0.y, w1.y);
            }
            int col = nt * 8 + 2 * tg;
            *(float2*)&sc[ra * 68 + col] =
                make_float2(fmaxf(c0 + b2s[col], 0.f), fmaxf(c1 + b2s[col + 1], 0.f));
            *(float2*)&sc[(ra + 8) * 68 + col] =
                make_float2(fmaxf(c2 + b2s[col], 0.f), fmaxf(c3 + b2s[col + 1], 0.f));
        }
        __syncthreads();

        // ---- segment-max over the sorted 160-row tile (5 groups x 32 rows) ----
        {
            int c  = tid & 63;
            int rs = (tid >> 6) * 32;
            float best = 0.f;
            int cur = -1;
            #pragma unroll 8
            for (int r = rs; r < rs + 32; r++) {
                int m = smm[r];
                float v = sc[r * 68 + c];
                if (m != cur) {
                    if (cur >= 0)
                        atomicMax(&outf[(size_t)cur * 64 + c], __float_as_int(best));
                    cur = m;
                    best = 0.f;
                }
                best = fmaxf(best, v);    // cur==-1 rows accumulate but never flush
            }
            if (cur >= 0)
                atomicMax(&outf[(size_t)cur * 64 + c], __float_as_int(best));
        }
    }
}

// ---------------------------------------------------------------------------
extern "C" void kernel_launch(void* const* d_in, const int* in_sizes, int n_in,
                              void* d_out, int out_size)
{
    const float* point_bxyz = (const float*)d_in[0];
    const float* point_feat = (const float*)d_in[1];
    const int*   sample_idx = (const int*)  d_in[2];
    const int*   e_point    = (const int*)  d_in[3];
    const int*   e_new      = (const int*)  d_in[4];
    const float* W1         = (const float*)d_in[5];
    const float* b1         = (const float*)d_in[6];
    const float* W2         = (const float*)d_in[7];
    const float* b2         = (const float*)d_in[8];

    float* out = (float*)d_out;
    int M = in_sizes[2];
    int E = in_sizes[3];

    cudaFuncSetAttribute(k_main_tc, cudaFuncAttributeMaxDynamicSharedMemorySize,
                         SMEM_WORDS * (int)sizeof(float));

    k_init_hist<<<2048, 256>>>((const float4*)point_bxyz, sample_idx, e_new,
                               W1, W2, out, M, E);

    int NB = (M + SCAN_BLK - 1) / SCAN_BLK;
    k_scan<<<NB, SCAN_BLK>>>(M);

    k_scatter<<<(E + 255) / 256, 256>>>(e_point, e_new, E);

    int nblk = (E + TILE * TPB - 1) / (TILE * TPB);
    k_main_tc<<<nblk, THREADS, SMEM_WORDS * sizeof(float)>>>(
        (const float4*)point_bxyz, (const float4*)point_feat,
        b1, b2,
        (const float4*)out,
        (int*)(out + 4 * (size_t)M),
        E, M);
}

// round 13
// speedup vs baseline: 1.2559x; 1.2559x over previous
#include <cuda_runtime.h>

// GraphConvDown: per-edge MLP (35 -> 64 -> 64) + scatter-max onto M sampled points.
// Round 13: fp16 asymmetric split. A (activations) = fp16 hi+lo (2 terms),
// B (weights) = single fp16. Error ~a*b_lo ~ 2^-11 => rel_err ~2-4e-4 (< 1e-3).
// vs R12: mma/warp-tile 168 -> 112, weight LDS wavefronts 224 -> 56, weight smem
// halved. Same TILE=160 / 320-thread / 3-block-per-SM shape.
//
// Output layout (float32): out[0..4M) = new_bxyz [M,4]; out[4M..4M+64M) = new_feat [M,64]

#define K1 35
#define MAXM 131072
#define MAXE 2000128
#define SCAN_BLK 1024
#define TILE 160
#define TPB 8
#define THREADS 320

// ---------- static scratch ----------
__device__ int      g_cnt[MAXM];
__device__ int      g_start[MAXM];
__device__ int      g_cursor[MAXM];
__device__ unsigned g_state[128];
__device__ int2     g_sorted[MAXE];
__device__ unsigned g_W1h[24 * 64];    // fp16x2 (k,k+1) pairs, k padded 35->48
__device__ unsigned g_W2h[32 * 64];    // k=64

// pack two floats to f16x2: low half = x (lower k), high half = y (k+1)
__device__ __forceinline__ unsigned pack_f16(float x, float y) {
    unsigned r;
    asm("cvt.rn.f16x2.f32 %0, %1, %2;" : "=r"(r) : "f"(y), "f"(x));
    return r;
}
__device__ __forceinline__ void split_f16(float x, float y, unsigned& hi, unsigned& lo) {
    hi = pack_f16(x, y);
    float hx, hy;
    asm("{ .reg .f16 a, b; mov.b32 {a, b}, %2; cvt.f32.f16 %0, a; cvt.f32.f16 %1, b; }"
        : "=f"(hx), "=f"(hy) : "r"(hi));
    lo = pack_f16(x - hx, y - hy);
}

// ---------------------------------------------------------------------------
// 1) init + weight pack (single fp16) + histogram
// ---------------------------------------------------------------------------
__global__ void k_init_hist(const float4* __restrict__ bxyz4,
                            const int* __restrict__ sample_idx,
                            const int* __restrict__ e_new,
                            const float* __restrict__ W1,
                            const float* __restrict__ W2,
                            float* __restrict__ out, int M, int E) {
    int i = blockIdx.x * blockDim.x + threadIdx.x;
    int stride = gridDim.x * blockDim.x;
    float4* ob = (float4*)out;
    for (int j = i; j < M; j += stride)
        ob[j] = bxyz4[sample_idx[j]];
    float4* fz = (float4*)(out + 4 * (size_t)M);
    int tot = M * 16;
    for (int j = i; j < tot; j += stride)
        fz[j] = make_float4(0.f, 0.f, 0.f, 0.f);
    for (int j = i; j < 24 * 64; j += stride) {
        int kp = j >> 6, n = j & 63;
        int k0 = 2 * kp, k1 = 2 * kp + 1;
        float w0 = (k0 < K1) ? W1[k0 * 64 + n] : 0.f;
        float w1 = (k1 < K1) ? W1[k1 * 64 + n] : 0.f;
        g_W1h[j] = pack_f16(w0, w1);
    }
    for (int j = i; j < 32 * 64; j += stride) {
        int kp = j >> 6, n = j & 63;
        g_W2h[j] = pack_f16(W2[(2 * kp) * 64 + n], W2[(2 * kp + 1) * 64 + n]);
    }
    for (int j = i; j < E; j += stride)
        atomicAdd(&g_cnt[e_new[j]], 1);
}

// ---------------------------------------------------------------------------
// 2) decoupled-lookback exclusive scan (123 blocks, single wave)
// ---------------------------------------------------------------------------
__global__ void k_scan(int M) {
    __shared__ int sh[SCAN_BLK];
    __shared__ int s_prefix;
    int bid = blockIdx.x;
    int tid = threadIdx.x;
    int i = bid * SCAN_BLK + tid;
    int c = (i < M) ? g_cnt[i] : 0;
    sh[tid] = c;
    __syncthreads();
    for (int d = 1; d < SCAN_BLK; d <<= 1) {
        int t = (tid >= d) ? sh[tid - d] : 0;
        __syncthreads();
        sh[tid] += t;
        __syncthreads();
    }
    int incl = sh[tid];
    if (tid == 0) {
        unsigned agg = (unsigned)sh[SCAN_BLK - 1];
        if (bid == 0) {
            atomicExch(&g_state[0], (2u << 30) | agg);
            s_prefix = 0;
        } else {
            atomicExch(&g_state[bid], (1u << 30) | agg);
            unsigned run = 0;
            int j = bid - 1;
            while (true) {
                unsigned s;
                do { s = atomicAdd(&g_state[j], 0u); } while ((s >> 30) == 0u);
                run += s & 0x3fffffffu;
                if ((s >> 30) == 2u) break;
                j--;
            }
            atomicExch(&g_state[bid], (2u << 30) | (run + agg));
            s_prefix = (int)run;
        }
    }
    __syncthreads();
    if (i < M) g_start[i] = s_prefix + incl - c;
}

// ---------------------------------------------------------------------------
// 3) counting-sort scatter
// ---------------------------------------------------------------------------
__global__ void k_scatter(const int* __restrict__ e_point,
                          const int* __restrict__ e_new, int E) {
    int i = blockIdx.x * blockDim.x + threadIdx.x;
    if (i < E) {
        int m = e_new[i];
        int pos = g_start[m] + atomicAdd(&g_cursor[m], 1);
        g_sorted[pos] = make_int2(e_point[i], m);
    }
}

// ---------------------------------------------------------------------------
__device__ __forceinline__ void mma_f16(float& c0, float& c1, float& c2, float& c3,
                                        unsigned a0, unsigned a1, unsigned a2, unsigned a3,
                                        unsigned b0, unsigned b1) {
    asm volatile("mma.sync.aligned.m16n8k16.row.col.f32.f16.f16.f32 "
                 "{%0,%1,%2,%3}, {%4,%5,%6,%7}, {%8,%9}, {%0,%1,%2,%3};"
                 : "+f"(c0), "+f"(c1), "+f"(c2), "+f"(c3)
                 : "r"(a0), "r"(a1), "r"(a2), "r"(a3), "r"(b0), "r"(b1));
}

// SMEM layout (32-bit word offsets).
// Weights: uint f16x2, row stride 72 -> bank 8*(tg+nt)+g, conflict-free.
#define S_W1   0                          // uint [24][72]
#define S_W2   (24 * 72)                  // uint [32][72]
#define W_END  (S_W2 + 32 * 72)           // 4032 words
#define S_B1   W_END
#define S_B2   (S_B1 + 64)
#define S_MM   (S_B2 + 64)                // [160] int
#define S_SC   (S_MM + 160)               // [160][68] f32
#define SMEM_WORDS (S_SC + 160 * 68)      // 15200 words = 60800 B -> 3 blocks/SM

// ---------------------------------------------------------------------------
// 4) main tensor-core kernel: 320 threads (10 warps), 160-edge tiles.
// ---------------------------------------------------------------------------
__global__ __launch_bounds__(THREADS, 3)
void k_main_tc(const float4* __restrict__ bxyz4,
               const float4* __restrict__ feat4,
               const float*  __restrict__ b1, const float* __restrict__ b2,
               const float4* __restrict__ newb4,
               int*          __restrict__ outf,
               int E, int M)
{
    extern __shared__ float sm[];
    unsigned* W1s = (unsigned*)sm + S_W1;
    unsigned* W2s = (unsigned*)sm + S_W2;
    float* b1s = sm + S_B1;
    float* b2s = sm + S_B2;
    int*   smm = (int*)(sm + S_MM);
    float* sc  = sm + S_SC;

    int tid  = threadIdx.x;
    int warp = tid >> 5;
    int lane = tid & 31;
    int g    = lane >> 2;
    int tg   = lane & 3;

    // ---- replay-state zeroing ----
    {
        int gt = blockIdx.x * THREADS + tid;
        if (gt < M) { g_cnt[gt] = 0; g_cursor[gt] = 0; }
        if (gt < 128) g_state[gt] = 0u;
    }

    // ---- stage weights (once per block) ----
    for (int i = tid; i < 24 * 64; i += THREADS) {
        int kp = i >> 6, n = i & 63;
        W1s[kp * 72 + n] = g_W1h[i];
    }
    for (int i = tid; i < 32 * 64; i += THREADS) {
        int kp = i >> 6, n = i & 63;
        W2s[kp * 72 + n] = g_W2h[i];
    }
    if (tid < 64) { b1s[tid] = b1[tid]; b2s[tid] = b2[tid]; }

    for (int tb = 0; tb < TPB; tb++) {
        int base = (blockIdx.x * TPB + tb) * TILE;
        if (base >= E) break;
        __syncthreads();    // prior epilogue done before sc/smm reuse

        // ---- stage 160 edge rows, 2 threads per row (warp-local rows) ----
        {
            int row  = tid >> 1;
            int half = tid & 1;
            int e = base + row;
            float* rp = sc + row * 68;
            if (e < E) {
                int2 em = g_sorted[e];
                int p = em.x, m = em.y;
                const float4* fp = feat4 + (size_t)p * 8;
                if (half == 0) {
                    smm[row] = m;
                    #pragma unroll
                    for (int q = 0; q < 4; q++) ((float4*)rp)[q] = fp[q];
                } else {
                    #pragma unroll
                    for (int q = 4; q < 8; q++) ((float4*)rp)[q] = fp[q];
                    float4 pb = bxyz4[p];
                    float4 nb = newb4[m];
                    ((float4*)rp)[8]  = make_float4(pb.y - nb.y, pb.z - nb.z, pb.w - nb.w, 0.f);
                    ((float4*)rp)[9]  = make_float4(0.f, 0.f, 0.f, 0.f);
                    ((float4*)rp)[10] = make_float4(0.f, 0.f, 0.f, 0.f);
                    ((float4*)rp)[11] = make_float4(0.f, 0.f, 0.f, 0.f);
                }
            } else {
                if (half == 0) {
                    smm[row] = -1;
                    #pragma unroll
                    for (int q = 0; q < 4; q++) ((float4*)rp)[q] = make_float4(0.f,0.f,0.f,0.f);
                } else {
                    #pragma unroll
                    for (int q = 4; q < 12; q++) ((float4*)rp)[q] = make_float4(0.f,0.f,0.f,0.f);
                }
            }
        }
        __syncwarp();       // staging rows and compute rows are warp-local

        int ra = warp * 16 + g;

        // ===== Layer 1, kf-outer, persistent accumulator bank; A=2 terms, B=1 =====
        float acc[8][4];
        #pragma unroll
        for (int nt = 0; nt < 8; nt++) {
            acc[nt][0] = 0.f; acc[nt][1] = 0.f; acc[nt][2] = 0.f; acc[nt][3] = 0.f;
        }
        #pragma unroll
        for (int kf = 0; kf < 3; kf++) {
            int k0 = kf * 16 + 2 * tg;
            float2 p0 = *(float2*)&sc[ra * 68 + k0];
            float2 p1 = *(float2*)&sc[(ra + 8) * 68 + k0];
            float2 p2 = *(float2*)&sc[ra * 68 + k0 + 8];
            float2 p3 = *(float2*)&sc[(ra + 8) * 68 + k0 + 8];
            unsigned ah0, ah1, ah2, ah3, al0, al1, al2, al3;
            split_f16(p0.x, p0.y, ah0, al0);
            split_f16(p1.x, p1.y, ah1, al1);
            split_f16(p2.x, p2.y, ah2, al2);
            split_f16(p3.x, p3.y, ah3, al3);
            #pragma unroll
            for (int nt = 0; nt < 8; nt++) {
                int nb = nt * 8 + g;
                unsigned w0 = W1s[(kf * 8 + tg) * 72 + nb];
                unsigned w1 = W1s[(kf * 8 + tg + 4) * 72 + nb];
                mma_f16(acc[nt][0], acc[nt][1], acc[nt][2], acc[nt][3], ah0, ah1, ah2, ah3, w0, w1);
                mma_f16(acc[nt][0], acc[nt][1], acc[nt][2], acc[nt][3], al0, al1, al2, al3, w0, w1);
            }
        }

        // ---- bias + relu + split: acc bank morphs into layer-2 A bank ----
        unsigned a2h[4][4], a2l[4][4];
        #pragma unroll
        for (int nt = 0; nt < 8; nt++) {
            int col = nt * 8 + 2 * tg;
            float v0 = fmaxf(acc[nt][0] + b1s[col], 0.f);
            float v1 = fmaxf(acc[nt][1] + b1s[col + 1], 0.f);
            float v2 = fmaxf(acc[nt][2] + b1s[col], 0.f);
            float v3 = fmaxf(acc[nt][3] + b1s[col + 1], 0.f);
            // C-frag (rows g/g+8, cols 8nt+2tg) == layer-2 A-frag kf2=nt>>1
            int kf2 = nt >> 1;
            int ix  = (nt & 1) * 2;
            split_f16(v0, v1, a2h[kf2][ix],     a2l[kf2][ix]);
            split_f16(v2, v3, a2h[kf2][ix + 1], a2l[kf2][ix + 1]);
        }

        // ===== Layer 2, nt-outer; A=2 terms, B=1; out -> sc =====
        #pragma unroll
        for (int nt = 0; nt < 8; nt++) {
            float c0 = 0.f, c1 = 0.f, c2 = 0.f, c3 = 0.f;
            int nb = nt * 8 + g;
            #pragma unroll
            for (int kf = 0; kf < 4; kf++) {
                unsigned w0 = W2s[(kf * 8 + tg) * 72 + nb];
                unsigned w1 = W2s[(kf * 8 + tg + 4) * 72 + nb];
                mma_f16(c0, c1, c2, c3, a2h[kf][0], a2h[kf][1], a2h[kf][2], a2h[kf][3], w0, w1);
                mma_f16(c0, c1, c2, c3, a2l[kf][0], a2l[kf][1], a2l[kf][2], a2l[kf][3], w0, w1);
            }
            int col = nt * 8 + 2 * tg;
            *(float2*)&sc[ra * 68 + col] =
                make_float2(fmaxf(c0 + b2s[col], 0.f), fmaxf(c1 + b2s[col + 1], 0.f));
            *(float2*)&sc[(ra + 8) * 68 + col] =
                make_float2(fmaxf(c2 + b2s[col], 0.f), fmaxf(c3 + b2s[col + 1], 0.f));
        }
        __syncthreads();

        // ---- segment-max over the sorted 160-row tile (5 groups x 32 rows) ----
        {
            int c  = tid & 63;
            int rs = (tid >> 6) * 32;
            float best = 0.f;
            int cur = -1;
            #pragma unroll 8
            for (int r = rs; r < rs + 32; r++) {
                int m = smm[r];
                float v = sc[r * 68 + c];
                if (m != cur) {
                    if (cur >= 0)
                        atomicMax(&outf[(size_t)cur * 64 + c], __float_as_int(best));
                    cur = m;
                    best = 0.f;
                }
                best = fmaxf(best, v);    // cur==-1 rows accumulate but never flush
            }
            if (cur >= 0)
                atomicMax(&outf[(size_t)cur * 64 + c], __float_as_int(best));
        }
    }
}

// ---------------------------------------------------------------------------
extern "C" void kernel_launch(void* const* d_in, const int* in_sizes, int n_in,
                              void* d_out, int out_size)
{
    const float* point_bxyz = (const float*)d_in[0];
    const float* point_feat = (const float*)d_in[1];
    const int*   sample_idx = (const int*)  d_in[2];
    const int*   e_point    = (const int*)  d_in[3];
    const int*   e_new      = (const int*)  d_in[4];
    const float* W1         = (const float*)d_in[5];
    const float* b1         = (const float*)d_in[6];
    const float* W2         = (const float*)d_in[7];
    const float* b2         = (const float*)d_in[8];

    float* out = (float*)d_out;
    int M = in_sizes[2];
    int E = in_sizes[3];

    cudaFuncSetAttribute(k_main_tc, cudaFuncAttributeMaxDynamicSharedMemorySize,
                         SMEM_WORDS * (int)sizeof(float));

    k_init_hist<<<2048, 256>>>((const float4*)point_bxyz, sample_idx, e_new,
                               W1, W2, out, M, E);

    int NB = (M + SCAN_BLK - 1) / SCAN_BLK;
    k_scan<<<NB, SCAN_BLK>>>(M);

    k_scatter<<<(E + 255) / 256, 256>>>(e_point, e_new, E);

    int nblk = (E + TILE * TPB - 1) / (TILE * TPB);
    k_main_tc<<<nblk, THREADS, SMEM_WORDS * sizeof(float)>>>(
        (const float4*)point_bxyz, (const float4*)point_feat,
        b1, b2,
        (const float4*)out,
        (int*)(out + 4 * (size_t)M),
        E, M);
}

// round 14
// speedup vs baseline: 1.2706x; 1.0117x over previous
#include <cuda_runtime.h>

// GraphConvDown: per-edge MLP (35 -> 64 -> 64) + scatter-max onto M sampled points.
// Round 14: fp16 asymmetric split (A = hi+lo, B = hi only) with the activation
// split PRECOMPUTED PER POINT in k_init_hist (g_fh/g_fl, packed f16x2 pairs).
// Staging copies packed uint4s directly into A-operand layout (no runtime split),
// layer-1 A fragments are direct LDS.32. Math bit-identical to R13 (1.89e-4).
//
// Output layout (float32): out[0..4M) = new_bxyz [M,4]; out[4M..4M+64M) = new_feat [M,64]

#define K1 35
#define MAXN 500000
#define MAXM 131072
#define MAXE 2000128
#define SCAN_BLK 1024
#define TILE 160
#define TPB 8
#define THREADS 320

// ---------- static scratch ----------
__device__ int      g_cnt[MAXM];
__device__ int      g_start[MAXM];
__device__ int      g_cursor[MAXM];
__device__ unsigned g_state[128];
__device__ int2     g_sorted[MAXE];
__device__ unsigned g_W1h[24 * 64];      // fp16x2 (k,k+1) pairs, k padded 35->48
__device__ unsigned g_W2h[32 * 64];      // k=64
__device__ unsigned g_fh[MAXN * 16];     // per-point feat fp16x2 hi pairs (32 feats -> 16 words)
__device__ unsigned g_fl[MAXN * 16];     // per-point feat fp16x2 lo pairs

// pack two floats to f16x2: low half = x (lower k), high half = y (k+1)
__device__ __forceinline__ unsigned pack_f16(float x, float y) {
    unsigned r;
    asm("cvt.rn.f16x2.f32 %0, %1, %2;" : "=r"(r) : "f"(y), "f"(x));
    return r;
}
__device__ __forceinline__ void split_f16(float x, float y, unsigned& hi, unsigned& lo) {
    hi = pack_f16(x, y);
    float hx, hy;
    asm("{ .reg .f16 a, b; mov.b32 {a, b}, %2; cvt.f32.f16 %0, a; cvt.f32.f16 %1, b; }"
        : "=f"(hx), "=f"(hy) : "r"(hi));
    lo = pack_f16(x - hx, y - hy);
}

// ---------------------------------------------------------------------------
// 1) init + weight pack + per-point feature split + histogram
// ---------------------------------------------------------------------------
__global__ void k_init_hist(const float4* __restrict__ bxyz4,
                            const int* __restrict__ sample_idx,
                            const int* __restrict__ e_new,
                            const float* __restrict__ point_feat,
                            const float* __restrict__ W1,
                            const float* __restrict__ W2,
                            float* __restrict__ out, int N, int M, int E) {
    int i = blockIdx.x * blockDim.x + threadIdx.x;
    int stride = gridDim.x * blockDim.x;
    float4* ob = (float4*)out;
    for (int j = i; j < M; j += stride)
        ob[j] = bxyz4[sample_idx[j]];
    float4* fz = (float4*)(out + 4 * (size_t)M);
    int tot = M * 16;
    for (int j = i; j < tot; j += stride)
        fz[j] = make_float4(0.f, 0.f, 0.f, 0.f);
    for (int j = i; j < 24 * 64; j += stride) {
        int kp = j >> 6, n = j & 63;
        int k0 = 2 * kp, k1 = 2 * kp + 1;
        float w0 = (k0 < K1) ? W1[k0 * 64 + n] : 0.f;
        float w1 = (k1 < K1) ? W1[k1 * 64 + n] : 0.f;
        g_W1h[j] = pack_f16(w0, w1);
    }
    for (int j = i; j < 32 * 64; j += stride) {
        int kp = j >> 6, n = j & 63;
        g_W2h[j] = pack_f16(W2[(2 * kp) * 64 + n], W2[(2 * kp + 1) * 64 + n]);
    }
    // per-point activation split: 16 packed pairs per point
    int nw = N * 16;
    for (int j = i; j < nw; j += stride) {
        int n = j >> 4, kp = j & 15;
        float2 f = *(const float2*)&point_feat[n * 32 + 2 * kp];
        unsigned hi, lo;
        split_f16(f.x, f.y, hi, lo);
        g_fh[j] = hi;
        g_fl[j] = lo;
    }
    for (int j = i; j < E; j += stride)
        atomicAdd(&g_cnt[e_new[j]], 1);
}

// ---------------------------------------------------------------------------
// 2) decoupled-lookback exclusive scan (123 blocks, single wave)
// ---------------------------------------------------------------------------
__global__ void k_scan(int M) {
    __shared__ int sh[SCAN_BLK];
    __shared__ int s_prefix;
    int bid = blockIdx.x;
    int tid = threadIdx.x;
    int i = bid * SCAN_BLK + tid;
    int c = (i < M) ? g_cnt[i] : 0;
    sh[tid] = c;
    __syncthreads();
    for (int d = 1; d < SCAN_BLK; d <<= 1) {
        int t = (tid >= d) ? sh[tid - d] : 0;
        __syncthreads();
        sh[tid] += t;
        __syncthreads();
    }
    int incl = sh[tid];
    if (tid == 0) {
        unsigned agg = (unsigned)sh[SCAN_BLK - 1];
        if (bid == 0) {
            atomicExch(&g_state[0], (2u << 30) | agg);
            s_prefix = 0;
        } else {
            atomicExch(&g_state[bid], (1u << 30) | agg);
            unsigned run = 0;
            int j = bid - 1;
            while (true) {
                unsigned s;
                do { s = atomicAdd(&g_state[j], 0u); } while ((s >> 30) == 0u);
                run += s & 0x3fffffffu;
                if ((s >> 30) == 2u) break;
                j--;
            }
            atomicExch(&g_state[bid], (2u << 30) | (run + agg));
            s_prefix = (int)run;
        }
    }
    __syncthreads();
    if (i < M) g_start[i] = s_prefix + incl - c;
}

// ---------------------------------------------------------------------------
// 3) counting-sort scatter
// ---------------------------------------------------------------------------
__global__ void k_scatter(const int* __restrict__ e_point,
                          const int* __restrict__ e_new, int E) {
    int i = blockIdx.x * blockDim.x + threadIdx.x;
    if (i < E) {
        int m = e_new[i];
        int pos = g_start[m] + atomicAdd(&g_cursor[m], 1);
        g_sorted[pos] = make_int2(e_point[i], m);
    }
}

// ---------------------------------------------------------------------------
__device__ __forceinline__ void mma_f16(float& c0, float& c1, float& c2, float& c3,
                                        unsigned a0, unsigned a1, unsigned a2, unsigned a3,
                                        unsigned b0, unsigned b1) {
    asm volatile("mma.sync.aligned.m16n8k16.row.col.f32.f16.f16.f32 "
                 "{%0,%1,%2,%3}, {%4,%5,%6,%7}, {%8,%9}, {%0,%1,%2,%3};"
                 : "+f"(c0), "+f"(c1), "+f"(c2), "+f"(c3)
                 : "r"(a0), "r"(a1), "r"(a2), "r"(a3), "r"(b0), "r"(b1));
}

// SMEM layout (32-bit word offsets).
// EF row (68 words): [0..24) hi pairs kp0..23, [24..48) lo pairs, [48..68) pad.
// Layer-2 output overwrites words [0..64) of the same row (safe: warp-local,
// EF consumed into registers before layer-2 writes).
#define S_W1   0                          // uint [24][72]
#define S_W2   (24 * 72)                  // uint [32][72]
#define W_END  (S_W2 + 32 * 72)           // 4032 words
#define S_B1   W_END
#define S_B2   (S_B1 + 64)
#define S_MM   (S_B2 + 64)                // [160] int
#define S_SC   (S_MM + 160)               // [160][68] words (u32/f32 views)
#define SMEM_WORDS (S_SC + 160 * 68)      // 15200 words = 60800 B -> 3 blocks/SM

// ---------------------------------------------------------------------------
// 4) main tensor-core kernel: 320 threads (10 warps), 160-edge tiles.
// ---------------------------------------------------------------------------
__global__ __launch_bounds__(THREADS, 3)
void k_main_tc(const float4* __restrict__ bxyz4,
               const float*  __restrict__ b1, const float* __restrict__ b2,
               const float4* __restrict__ newb4,
               int*          __restrict__ outf,
               int E, int M)
{
    extern __shared__ float sm[];
    unsigned* W1s = (unsigned*)sm + S_W1;
    unsigned* W2s = (unsigned*)sm + S_W2;
    float* b1s = sm + S_B1;
    float* b2s = sm + S_B2;
    int*   smm = (int*)(sm + S_MM);
    float* sc  = sm + S_SC;
    unsigned* scu = (unsigned*)sm + S_SC;

    int tid  = threadIdx.x;
    int warp = tid >> 5;
    int lane = tid & 31;
    int g    = lane >> 2;
    int tg   = lane & 3;

    // ---- replay-state zeroing ----
    {
        int gt = blockIdx.x * THREADS + tid;
        if (gt < M) { g_cnt[gt] = 0; g_cursor[gt] = 0; }
        if (gt < 128) g_state[gt] = 0u;
    }

    // ---- stage weights (once per block) ----
    for (int i = tid; i < 24 * 64; i += THREADS) {
        int kp = i >> 6, n = i & 63;
        W1s[kp * 72 + n] = g_W1h[i];
    }
    for (int i = tid; i < 32 * 64; i += THREADS) {
        int kp = i >> 6, n = i & 63;
        W2s[kp * 72 + n] = g_W2h[i];
    }
    if (tid < 64) { b1s[tid] = b1[tid]; b2s[tid] = b2[tid]; }

    for (int tb = 0; tb < TPB; tb++) {
        int base = (blockIdx.x * TPB + tb) * TILE;
        if (base >= E) break;
        __syncthreads();    // prior epilogue done before sc/smm reuse

        // ---- stage 160 edge rows, 2 threads per row (warp-local rows) ----
        {
            int row  = tid >> 1;
            int half = tid & 1;
            int e = base + row;
            unsigned* rp = scu + row * 68;
            if (e < E) {
                int2 em = g_sorted[e];
                int p = em.x, m = em.y;
                if (half == 0) {
                    smm[row] = m;
                    const uint4* fh = (const uint4*)(g_fh + (size_t)p * 16);
                    #pragma unroll
                    for (int q = 0; q < 4; q++) ((uint4*)rp)[q] = fh[q];      // hi kp0..15
                } else {
                    const uint4* fl = (const uint4*)(g_fl + (size_t)p * 16);
                    #pragma unroll
                    for (int q = 0; q < 4; q++) ((uint4*)(rp + 24))[q] = fl[q];  // lo kp0..15
                    float4 pb = bxyz4[p];
                    float4 nb = newb4[m];
                    unsigned h0, l0, h1, l1;
                    split_f16(pb.y - nb.y, pb.z - nb.z, h0, l0);   // (rx, ry)
                    split_f16(pb.w - nb.w, 0.f, h1, l1);           // (rz, 0)
                    ((uint4*)rp)[4]        = make_uint4(h0, h1, 0u, 0u);   // hi kp16..19
                    ((uint4*)rp)[5]        = make_uint4(0u, 0u, 0u, 0u);   // hi kp20..23
                    ((uint4*)(rp + 24))[4] = make_uint4(l0, l1, 0u, 0u);   // lo kp16..19
                    ((uint4*)(rp + 24))[5] = make_uint4(0u, 0u, 0u, 0u);   // lo kp20..23
                }
            } else {
                if (half == 0) {
                    smm[row] = -1;
                    #pragma unroll
                    for (int q = 0; q < 4; q++) ((uint4*)rp)[q] = make_uint4(0u,0u,0u,0u);
                } else {
                    #pragma unroll
                    for (int q = 4; q < 6; q++) ((uint4*)rp)[q] = make_uint4(0u,0u,0u,0u);
                    #pragma unroll
                    for (int q = 0; q < 6; q++) ((uint4*)(rp + 24))[q] = make_uint4(0u,0u,0u,0u);
                }
            }
        }
        __syncwarp();       // staging rows and compute rows are warp-local

        int ra = warp * 16 + g;

        // ===== Layer 1, kf-outer, persistent accumulator bank; A=2 terms, B=1 =====
        float acc[8][4];
        #pragma unroll
        for (int nt = 0; nt < 8; nt++) {
            acc[nt][0] = 0.f; acc[nt][1] = 0.f; acc[nt][2] = 0.f; acc[nt][3] = 0.f;
        }
        #pragma unroll
        for (int kf = 0; kf < 3; kf++) {
            int kp = kf * 8 + tg;
            unsigned ah0 = scu[ra * 68 + kp];
            unsigned ah1 = scu[(ra + 8) * 68 + kp];
            unsigned ah2 = scu[ra * 68 + kp + 4];
            unsigned ah3 = scu[(ra + 8) * 68 + kp + 4];
            unsigned al0 = scu[ra * 68 + 24 + kp];
            unsigned al1 = scu[(ra + 8) * 68 + 24 + kp];
            unsigned al2 = scu[ra * 68 + 24 + kp + 4];
            unsigned al3 = scu[(ra + 8) * 68 + 24 + kp + 4];
            #pragma unroll
            for (int nt = 0; nt < 8; nt++) {
                int nb = nt * 8 + g;
                unsigned w0 = W1s[kp * 72 + nb];
                unsigned w1 = W1s[(kp + 4) * 72 + nb];
                mma_f16(acc[nt][0], acc[nt][1], acc[nt][2], acc[nt][3], ah0, ah1, ah2, ah3, w0, w1);
                mma_f16(acc[nt][0], acc[nt][1], acc[nt][2], acc[nt][3], al0, al1, al2, al3, w0, w1);
            }
        }

        // ---- bias + relu + split: acc bank morphs into layer-2 A bank ----
        unsigned a2h[4][4], a2l[4][4];
        #pragma unroll
        for (int nt = 0; nt < 8; nt++) {
            int col = nt * 8 + 2 * tg;
            float v0 = fmaxf(acc[nt][0] + b1s[col], 0.f);
            float v1 = fmaxf(acc[nt][1] + b1s[col + 1], 0.f);
            float v2 = fmaxf(acc[nt][2] + b1s[col], 0.f);
            float v3 = fmaxf(acc[nt][3] + b1s[col + 1], 0.f);
            // C-frag (rows g/g+8, cols 8nt+2tg) == layer-2 A-frag kf2=nt>>1
            int kf2 = nt >> 1;
            int ix  = (nt & 1) * 2;
            split_f16(v0, v1, a2h[kf2][ix],     a2l[kf2][ix]);
            split_f16(v2, v3, a2h[kf2][ix + 1], a2l[kf2][ix + 1]);
        }

        // ===== Layer 2, nt-outer; A=2 terms, B=1; out -> sc rows (overlays EF) =====
        #pragma unroll
        for (int nt = 0; nt < 8; nt++) {
            float c0 = 0.f, c1 = 0.f, c2 = 0.f, c3 = 0.f;
            int nb = nt * 8 + g;
            #pragma unroll
            for (int kf = 0; kf < 4; kf++) {
                unsigned w0 = W2s[(kf * 8 + tg) * 72 + nb];
                unsigned w1 = W2s[(kf * 8 + tg + 4) * 72 + nb];
                mma_f16(c0, c1, c2, c3, a2h[kf][0], a2h[kf][1], a2h[kf][2], a2h[kf][3], w0, w1);
                mma_f16(c0, c1, c2, c3, a2l[kf][0], a2l[kf][1], a2l[kf][2], a2l[kf][3], w0, w1);
            }
            int col = nt * 8 + 2 * tg;
            *(float2*)&sc[ra * 68 + col] =
                make_float2(fmaxf(c0 + b2s[col], 0.f), fmaxf(c1 + b2s[col + 1], 0.f));
            *(float2*)&sc[(ra + 8) * 68 + col] =
                make_float2(fmaxf(c2 + b2s[col], 0.f), fmaxf(c3 + b2s[col + 1], 0.f));
        }
        __syncthreads();

        // ---- segment-max over the sorted 160-row tile (5 groups x 32 rows) ----
        {
            int c  = tid & 63;
            int rs = (tid >> 6) * 32;
            float best = 0.f;
            int cur = -1;
            #pragma unroll 8
            for (int r = rs; r < rs + 32; r++) {
                int m = smm[r];
                float v = sc[r * 68 + c];
                if (m != cur) {
                    if (cur >= 0)
                        atomicMax(&outf[(size_t)cur * 64 + c], __float_as_int(best));
                    cur = m;
                    best = 0.f;
                }
                best = fmaxf(best, v);    // cur==-1 rows accumulate but never flush
            }
            if (cur >= 0)
                atomicMax(&outf[(size_t)cur * 64 + c], __float_as_int(best));
        }
    }
}

// ---------------------------------------------------------------------------
extern "C" void kernel_launch(void* const* d_in, const int* in_sizes, int n_in,
                              void* d_out, int out_size)
{
    const float* point_bxyz = (const float*)d_in[0];
    const float* point_feat = (const float*)d_in[1];
    const int*   sample_idx = (const int*)  d_in[2];
    const int*   e_point    = (const int*)  d_in[3];
    const int*   e_new      = (const int*)  d_in[4];
    const float* W1         = (const float*)d_in[5];
    const float* b1         = (const float*)d_in[6];
    const float* W2         = (const float*)d_in[7];
    const float* b2         = (const float*)d_in[8];

    float* out = (float*)d_out;
    int N = in_sizes[0] / 4;
    int M = in_sizes[2];
    int E = in_sizes[3];

    cudaFuncSetAttribute(k_main_tc, cudaFuncAttributeMaxDynamicSharedMemorySize,
                         SMEM_WORDS * (int)sizeof(float));

    k_init_hist<<<2048, 256>>>((const float4*)point_bxyz, sample_idx, e_new,
                               point_feat, W1, W2, out, N, M, E);

    int NB = (M + SCAN_BLK - 1) / SCAN_BLK;
    k_scan<<<NB, SCAN_BLK>>>(M);

    k_scatter<<<(E + 255) / 256, 256>>>(e_point, e_new, E);

    int nblk = (E + TILE * TPB - 1) / (TILE * TPB);
    k_main_tc<<<nblk, THREADS, SMEM_WORDS * sizeof(float)>>>(
        (const float4*)point_bxyz,
        b1, b2,
        (const float4*)out,
        (int*)(out + 4 * (size_t)M),
        E, M);
}

// round 15
// speedup vs baseline: 1.4085x; 1.1085x over previous
#include <cuda_runtime.h>

// GraphConvDown: per-edge MLP (35 -> 64 -> 64) + scatter-max onto M sampled points.
// Round 15: line-coherent activation gathers (one 128B block per point, 8 lanes
// cooperatively fetch one point -> warp instruction touches 4 lines not ~32) and
// paired weight LDS.64 (kp/kp+4 as uint2, conflict-free stride-68 layout).
// Math bit-identical to R13/R14 (fp16 asymmetric split): rel_err 1.89e-4.
//
// Output layout (float32): out[0..4M) = new_bxyz [M,4]; out[4M..4M+64M) = new_feat [M,64]

#define K1 35
#define MAXN 500000
#define MAXM 131072
#define MAXE 2000128
#define SCAN_BLK 1024
#define TILE 160
#define TPB 8
#define THREADS 320

// ---------- static scratch ----------
__device__ int      g_cnt[MAXM];
__device__ int      g_start[MAXM];
__device__ int      g_cursor[MAXM];
__device__ unsigned g_state[128];
__device__ int2     g_sorted[MAXE];
__device__ uint2    g_W1p[12 * 64];      // (w[kp], w[kp+4]) f16x2 pairs, kp = kf*8+tg
__device__ uint2    g_W2p[16 * 64];
__device__ __align__(128) uint4 g_fi[MAXN * 8];   // per-point: words 0..15 hi pairs, 16..31 lo pairs

// pack two floats to f16x2: low half = x (lower k), high half = y (k+1)
__device__ __forceinline__ unsigned pack_f16(float x, float y) {
    unsigned r;
    asm("cvt.rn.f16x2.f32 %0, %1, %2;" : "=r"(r) : "f"(y), "f"(x));
    return r;
}
__device__ __forceinline__ void split_f16(float x, float y, unsigned& hi, unsigned& lo) {
    hi = pack_f16(x, y);
    float hx, hy;
    asm("{ .reg .f16 a, b; mov.b32 {a, b}, %2; cvt.f32.f16 %0, a; cvt.f32.f16 %1, b; }"
        : "=f"(hx), "=f"(hy) : "r"(hi));
    lo = pack_f16(x - hx, y - hy);
}

// ---------------------------------------------------------------------------
// 1) init + paired weight pack + per-point feature split + histogram
// ---------------------------------------------------------------------------
__global__ void k_init_hist(const float4* __restrict__ bxyz4,
                            const int* __restrict__ sample_idx,
                            const int* __restrict__ e_new,
                            const float* __restrict__ point_feat,
                            const float* __restrict__ W1,
                            const float* __restrict__ W2,
                            float* __restrict__ out, int N, int M, int E) {
    int i = blockIdx.x * blockDim.x + threadIdx.x;
    int stride = gridDim.x * blockDim.x;
    float4* ob = (float4*)out;
    for (int j = i; j < M; j += stride)
        ob[j] = bxyz4[sample_idx[j]];
    float4* fz = (float4*)(out + 4 * (size_t)M);
    int tot = M * 16;
    for (int j = i; j < tot; j += stride)
        fz[j] = make_float4(0.f, 0.f, 0.f, 0.f);
    // W1 pairs: row = kf*4+tg (kf 0..2), pair (kp, kp+4), kp = kf*8+tg; k padded 35->48
    for (int j = i; j < 12 * 64; j += stride) {
        int row = j >> 6, nb = j & 63;
        int kf = row >> 2, tg = row & 3;
        int kp = kf * 8 + tg;
        int ka = 2 * kp, kb = 2 * kp + 1;
        float a0 = (ka < K1) ? W1[ka * 64 + nb] : 0.f;
        float a1 = (kb < K1) ? W1[kb * 64 + nb] : 0.f;
        int kc = 2 * (kp + 4), kd = 2 * (kp + 4) + 1;
        float c0 = (kc < K1) ? W1[kc * 64 + nb] : 0.f;
        float c1 = (kd < K1) ? W1[kd * 64 + nb] : 0.f;
        g_W1p[j] = make_uint2(pack_f16(a0, a1), pack_f16(c0, c1));
    }
    for (int j = i; j < 16 * 64; j += stride) {
        int row = j >> 6, nb = j & 63;
        int kf = row >> 2, tg = row & 3;
        int kp = kf * 8 + tg;
        g_W2p[j] = make_uint2(
            pack_f16(W2[(2 * kp) * 64 + nb],       W2[(2 * kp + 1) * 64 + nb]),
            pack_f16(W2[(2 * (kp + 4)) * 64 + nb], W2[(2 * (kp + 4) + 1) * 64 + nb]));
    }
    // per-point activation split -> one 128B block per point
    unsigned* fiw = (unsigned*)g_fi;
    int nw = N * 16;
    for (int j = i; j < nw; j += stride) {
        int n = j >> 4, kp = j & 15;
        float2 f = *(const float2*)&point_feat[n * 32 + 2 * kp];
        unsigned hi, lo;
        split_f16(f.x, f.y, hi, lo);
        fiw[(size_t)n * 32 + kp] = hi;
        fiw[(size_t)n * 32 + 16 + kp] = lo;
    }
    for (int j = i; j < E; j += stride)
        atomicAdd(&g_cnt[e_new[j]], 1);
}

// ---------------------------------------------------------------------------
// 2) decoupled-lookback exclusive scan (123 blocks, single wave)
// ---------------------------------------------------------------------------
__global__ void k_scan(int M) {
    __shared__ int sh[SCAN_BLK];
    __shared__ int s_prefix;
    int bid = blockIdx.x;
    int tid = threadIdx.x;
    int i = bid * SCAN_BLK + tid;
    int c = (i < M) ? g_cnt[i] : 0;
    sh[tid] = c;
    __syncthreads();
    for (int d = 1; d < SCAN_BLK; d <<= 1) {
        int t = (tid >= d) ? sh[tid - d] : 0;
        __syncthreads();
        sh[tid] += t;
        __syncthreads();
    }
    int incl = sh[tid];
    if (tid == 0) {
        unsigned agg = (unsigned)sh[SCAN_BLK - 1];
        if (bid == 0) {
            atomicExch(&g_state[0], (2u << 30) | agg);
            s_prefix = 0;
        } else {
            atomicExch(&g_state[bid], (1u << 30) | agg);
            unsigned run = 0;
            int j = bid - 1;
            while (true) {
                unsigned s;
                do { s = atomicAdd(&g_state[j], 0u); } while ((s >> 30) == 0u);
                run += s & 0x3fffffffu;
                if ((s >> 30) == 2u) break;
                j--;
            }
            atomicExch(&g_state[bid], (2u << 30) | (run + agg));
            s_prefix = (int)run;
        }
    }
    __syncthreads();
    if (i < M) g_start[i] = s_prefix + incl - c;
}

// ---------------------------------------------------------------------------
// 3) counting-sort scatter
// ---------------------------------------------------------------------------
__global__ void k_scatter(const int* __restrict__ e_point,
                          const int* __restrict__ e_new, int E) {
    int i = blockIdx.x * blockDim.x + threadIdx.x;
    if (i < E) {
        int m = e_new[i];
        int pos = g_start[m] + atomicAdd(&g_cursor[m], 1);
        g_sorted[pos] = make_int2(e_point[i], m);
    }
}

// ---------------------------------------------------------------------------
__device__ __forceinline__ void mma_f16(float& c0, float& c1, float& c2, float& c3,
                                        unsigned a0, unsigned a1, unsigned a2, unsigned a3,
                                        unsigned b0, unsigned b1) {
    asm volatile("mma.sync.aligned.m16n8k16.row.col.f32.f16.f16.f32 "
                 "{%0,%1,%2,%3}, {%4,%5,%6,%7}, {%8,%9}, {%0,%1,%2,%3};"
                 : "+f"(c0), "+f"(c1), "+f"(c2), "+f"(c3)
                 : "r"(a0), "r"(a1), "r"(a2), "r"(a3), "r"(b0), "r"(b1));
}

// SMEM layout (32-bit word offsets).
// Weight pairs: uint2, row stride 68 (uint2 units) -> per-16-lane-phase banks
// 8tg+16nt+2g+const, all distinct -> conflict-free LDS.64.
// EF row (68 words): [0..16) hi feat, [16..24) hi rel+pad, [24..40) lo feat,
// [40..48) lo rel+pad; layer-2 output overwrites [0..64).
#define S_W1   0                           // uint2 [12][68] -> 1632 words
#define S_W2   1632                        // uint2 [16][68] -> 2176 words
#define S_B1   3808
#define S_B2   (S_B1 + 64)
#define S_MM   (S_B2 + 64)                 // [160] int
#define S_P    (S_MM + 160)                // [160] int (point index per row)
#define S_SC   (S_P + 160)                 // [160][68] words
#define SMEM_WORDS (S_SC + 160 * 68)       // 15136 words = 60544 B -> 3 blocks/SM

// ---------------------------------------------------------------------------
// 4) main tensor-core kernel: 320 threads (10 warps), 160-edge tiles.
// ---------------------------------------------------------------------------
__global__ __launch_bounds__(THREADS, 3)
void k_main_tc(const float4* __restrict__ bxyz4,
               const float*  __restrict__ b1, const float* __restrict__ b2,
               const float4* __restrict__ newb4,
               int*          __restrict__ outf,
               int E, int M)
{
    extern __shared__ float sm[];
    uint2* W1ps = (uint2*)(sm + S_W1);
    uint2* W2ps = (uint2*)(sm + S_W2);
    float* b1s = sm + S_B1;
    float* b2s = sm + S_B2;
    int*   smm = (int*)(sm + S_MM);
    int*   s_p = (int*)(sm + S_P);
    float* sc  = sm + S_SC;
    unsigned* scu = (unsigned*)sm + S_SC;

    int tid  = threadIdx.x;
    int warp = tid >> 5;
    int lane = tid & 31;
    int g    = lane >> 2;
    int tg   = lane & 3;

    // ---- replay-state zeroing ----
    {
        int gt = blockIdx.x * THREADS + tid;
        if (gt < M) { g_cnt[gt] = 0; g_cursor[gt] = 0; }
        if (gt < 128) g_state[gt] = 0u;
    }

    // ---- stage weight pairs (once per block) ----
    for (int i = tid; i < 12 * 64; i += THREADS) {
        int row = i >> 6, nb = i & 63;
        W1ps[row * 68 + nb] = g_W1p[i];
    }
    for (int i = tid; i < 16 * 64; i += THREADS) {
        int row = i >> 6, nb = i & 63;
        W2ps[row * 68 + nb] = g_W2p[i];
    }
    if (tid < 64) { b1s[tid] = b1[tid]; b2s[tid] = b2[tid]; }

    for (int tb = 0; tb < TPB; tb++) {
        int base = (blockIdx.x * TPB + tb) * TILE;
        if (base >= E) break;
        __syncthreads();    // prior epilogue done before smem tile reuse

        // ---- step A: indices + rel-pos (threads 0..159, one per row) ----
        if (tid < TILE) {
            int r = tid;
            int e = base + r;
            unsigned* rp = scu + r * 68;
            if (e < E) {
                int2 em = g_sorted[e];
                s_p[r] = em.x;
                smm[r] = em.y;
                float4 pb = bxyz4[em.x];
                float4 nb = newb4[em.y];
                unsigned h0, l0, h1, l1;
                split_f16(pb.y - nb.y, pb.z - nb.z, h0, l0);   // (rx, ry)
                split_f16(pb.w - nb.w, 0.f, h1, l1);           // (rz, 0)
                ((uint4*)rp)[4]  = make_uint4(h0, h1, 0u, 0u); // hi kp16..19
                ((uint4*)rp)[5]  = make_uint4(0u, 0u, 0u, 0u); // hi kp20..23
                ((uint4*)rp)[10] = make_uint4(l0, l1, 0u, 0u); // lo kp16..19
                ((uint4*)rp)[11] = make_uint4(0u, 0u, 0u, 0u); // lo kp20..23
            } else {
                s_p[r] = -1;
                smm[r] = -1;
                ((uint4*)rp)[4]  = make_uint4(0u, 0u, 0u, 0u);
                ((uint4*)rp)[5]  = make_uint4(0u, 0u, 0u, 0u);
                ((uint4*)rp)[10] = make_uint4(0u, 0u, 0u, 0u);
                ((uint4*)rp)[11] = make_uint4(0u, 0u, 0u, 0u);
            }
        }
        __syncthreads();

        // ---- step B: cooperative feature gather (warp-local rows) ----
        // 8 lanes fetch one point's 128B block; warp instruction touches 4 lines.
        {
            int q = lane & 7;               // uint4 index within point block
            int ro = lane >> 3;             // row offset within group of 4
            #pragma unroll
            for (int it = 0; it < 4; it++) {
                int r = warp * 16 + it * 4 + ro;
                int p = s_p[r];
                uint4 v = (p >= 0) ? g_fi[(size_t)p * 8 + q]
                                   : make_uint4(0u, 0u, 0u, 0u);
                // dst: hi feat at words [0..16), lo feat at [24..40)
                int dw = (q < 4) ? q * 4 : q * 4 + 8;
                *(uint4*)(scu + r * 68 + dw) = v;
            }
        }
        __syncwarp();       // gathered rows are the rows this warp computes

        int ra = warp * 16 + g;

        // ===== Layer 1, kf-outer, persistent accumulator bank; A=2 terms, B=1 =====
        float acc[8][4];
        #pragma unroll
        for (int nt = 0; nt < 8; nt++) {
            acc[nt][0] = 0.f; acc[nt][1] = 0.f; acc[nt][2] = 0.f; acc[nt][3] = 0.f;
        }
        #pragma unroll
        for (int kf = 0; kf < 3; kf++) {
            int kp = kf * 8 + tg;
            unsigned ah0 = scu[ra * 68 + kp];
            unsigned ah1 = scu[(ra + 8) * 68 + kp];
            unsigned ah2 = scu[ra * 68 + kp + 4];
            unsigned ah3 = scu[(ra + 8) * 68 + kp + 4];
            unsigned al0 = scu[ra * 68 + 24 + kp];
            unsigned al1 = scu[(ra + 8) * 68 + 24 + kp];
            unsigned al2 = scu[ra * 68 + 24 + kp + 4];
            unsigned al3 = scu[(ra + 8) * 68 + 24 + kp + 4];
            int wrow = kf * 4 + tg;
            #pragma unroll
            for (int nt = 0; nt < 8; nt++) {
                int nb = nt * 8 + g;
                uint2 w = W1ps[wrow * 68 + nb];
                mma_f16(acc[nt][0], acc[nt][1], acc[nt][2], acc[nt][3], ah0, ah1, ah2, ah3, w.x, w.y);
                mma_f16(acc[nt][0], acc[nt][1], acc[nt][2], acc[nt][3], al0, al1, al2, al3, w.x, w.y);
            }
        }

        // ---- bias + relu + split: acc bank morphs into layer-2 A bank ----
        unsigned a2h[4][4], a2l[4][4];
        #pragma unroll
        for (int nt = 0; nt < 8; nt++) {
            int col = nt * 8 + 2 * tg;
            float v0 = fmaxf(acc[nt][0] + b1s[col], 0.f);
            float v1 = fmaxf(acc[nt][1] + b1s[col + 1], 0.f);
            float v2 = fmaxf(acc[nt][2] + b1s[col], 0.f);
            float v3 = fmaxf(acc[nt][3] + b1s[col + 1], 0.f);
            // C-frag (rows g/g+8, cols 8nt+2tg) == layer-2 A-frag kf2=nt>>1
            int kf2 = nt >> 1;
            int ix  = (nt & 1) * 2;
            split_f16(v0, v1, a2h[kf2][ix],     a2l[kf2][ix]);
            split_f16(v2, v3, a2h[kf2][ix + 1], a2l[kf2][ix + 1]);
        }

        // ===== Layer 2, nt-outer; A=2 terms, B=1; out -> sc rows (overlays EF) =====
        #pragma unroll
        for (int nt = 0; nt < 8; nt++) {
            float c0 = 0.f, c1 = 0.f, c2 = 0.f, c3 = 0.f;
            int nb = nt * 8 + g;
            #pragma unroll
            for (int kf = 0; kf < 4; kf++) {
                uint2 w = W2ps[(kf * 4 + tg) * 68 + nb];
                mma_f16(c0, c1, c2, c3, a2h[kf][0], a2h[kf][1], a2h[kf][2], a2h[kf][3], w.x, w.y);
                mma_f16(c0, c1, c2, c3, a2l[kf][0], a2l[kf][1], a2l[kf][2], a2l[kf][3], w.x, w.y);
            }
            int col = nt * 8 + 2 * tg;
            *(float2*)&sc[ra * 68 + col] =
                make_float2(fmaxf(c0 + b2s[col], 0.f), fmaxf(c1 + b2s[col + 1], 0.f));
            *(float2*)&sc[(ra + 8) * 68 + col] =
                make_float2(fmaxf(c2 + b2s[col], 0.f), fmaxf(c3 + b2s[col + 1], 0.f));
        }
        __syncthreads();

        // ---- segment-max over the sorted 160-row tile (5 groups x 32 rows) ----
        {
            int c  = tid & 63;
            int rs = (tid >> 6) * 32;
            float best = 0.f;
            int cur = -1;
            #pragma unroll 8
            for (int r = rs; r < rs + 32; r++) {
                int m = smm[r];
                float v = sc[r * 68 + c];
                if (m != cur) {
                    if (cur >= 0)
                        atomicMax(&outf[(size_t)cur * 64 + c], __float_as_int(best));
                    cur = m;
                    best = 0.f;
                }
                best = fmaxf(best, v);    // cur==-1 rows accumulate but never flush
            }
            if (cur >= 0)
                atomicMax(&outf[(size_t)cur * 64 + c], __float_as_int(best));
        }
    }
}

// ---------------------------------------------------------------------------
extern "C" void kernel_launch(void* const* d_in, const int* in_sizes, int n_in,
                              void* d_out, int out_size)
{
    const float* point_bxyz = (const float*)d_in[0];
    const float* point_feat = (const float*)d_in[1];
    const int*   sample_idx = (const int*)  d_in[2];
    const int*   e_point    = (const int*)  d_in[3];
    const int*   e_new      = (const int*)  d_in[4];
    const float* W1         = (const float*)d_in[5];
    const float* b1         = (const float*)d_in[6];
    const float* W2         = (const float*)d_in[7];
    const float* b2         = (const float*)d_in[8];

    float* out = (float*)d_out;
    int N = in_sizes[0] / 4;
    int M = in_sizes[2];
    int E = in_sizes[3];

    cudaFuncSetAttribute(k_main_tc, cudaFuncAttributeMaxDynamicSharedMemorySize,
                         SMEM_WORDS * (int)sizeof(float));

    k_init_hist<<<2048, 256>>>((const float4*)point_bxyz, sample_idx, e_new,
                               point_feat, W1, W2, out, N, M, E);

    int NB = (M + SCAN_BLK - 1) / SCAN_BLK;
    k_scan<<<NB, SCAN_BLK>>>(M);

    k_scatter<<<(E + 255) / 256, 256>>>(e_point, e_new, E);

    int nblk = (E + TILE * TPB - 1) / (TILE * TPB);
    k_main_tc<<<nblk, THREADS, SMEM_WORDS * sizeof(float)>>>(
        (const float4*)point_bxyz,
        b1, b2,
        (const float4*)out,
        (int*)(out + 4 * (size_t)M),
        E, M);
}

// round 17
// speedup vs baseline: 1.4162x; 1.0055x over previous
#include <cuda_runtime.h>

// GraphConvDown: per-edge MLP (35 -> 64 -> 64) + scatter-max onto M sampled points.
// Round 17 (= R16 resubmitted after infra failure; no code change).
// TILE=128 / 256 threads / launch_bounds(256,4): smem 51.3 KB -> 4 blocks/SM
// (32 warps, occ 50% vs 43%), staging fully warp-local (one fewer __syncthreads
// per tile). Math identical to R13-R15 (fp16 asymmetric split, line-coherent
// gathers): rel_err 1.89e-4.
//
// Output layout (float32): out[0..4M) = new_bxyz [M,4]; out[4M..4M+64M) = new_feat [M,64]

#define K1 35
#define MAXN 500000
#define MAXM 131072
#define MAXE 2000128
#define SCAN_BLK 1024
#define TILE 128
#define TPB 8
#define THREADS 256

// ---------- static scratch ----------
__device__ int      g_cnt[MAXM];
__device__ int      g_start[MAXM];
__device__ int      g_cursor[MAXM];
__device__ unsigned g_state[128];
__device__ int2     g_sorted[MAXE];
__device__ uint2    g_W1p[12 * 64];      // (w[kp], w[kp+4]) f16x2 pairs, kp = kf*8+tg
__device__ uint2    g_W2p[16 * 64];
__device__ __align__(128) uint4 g_fi[MAXN * 8];   // per-point: words 0..15 hi pairs, 16..31 lo pairs

// pack two floats to f16x2: low half = x (lower k), high half = y (k+1)
__device__ __forceinline__ unsigned pack_f16(float x, float y) {
    unsigned r;
    asm("cvt.rn.f16x2.f32 %0, %1, %2;" : "=r"(r) : "f"(y), "f"(x));
    return r;
}
__device__ __forceinline__ void split_f16(float x, float y, unsigned& hi, unsigned& lo) {
    hi = pack_f16(x, y);
    float hx, hy;
    asm("{ .reg .f16 a, b; mov.b32 {a, b}, %2; cvt.f32.f16 %0, a; cvt.f32.f16 %1, b; }"
        : "=f"(hx), "=f"(hy) : "r"(hi));
    lo = pack_f16(x - hx, y - hy);
}

// ---------------------------------------------------------------------------
// 1) init + paired weight pack + per-point feature split + histogram
// ---------------------------------------------------------------------------
__global__ void k_init_hist(const float4* __restrict__ bxyz4,
                            const int* __restrict__ sample_idx,
                            const int* __restrict__ e_new,
                            const float* __restrict__ point_feat,
                            const float* __restrict__ W1,
                            const float* __restrict__ W2,
                            float* __restrict__ out, int N, int M, int E) {
    int i = blockIdx.x * blockDim.x + threadIdx.x;
    int stride = gridDim.x * blockDim.x;
    float4* ob = (float4*)out;
    for (int j = i; j < M; j += stride)
        ob[j] = bxyz4[sample_idx[j]];
    float4* fz = (float4*)(out + 4 * (size_t)M);
    int tot = M * 16;
    for (int j = i; j < tot; j += stride)
        fz[j] = make_float4(0.f, 0.f, 0.f, 0.f);
    // W1 pairs: row = kf*4+tg (kf 0..2), pair (kp, kp+4), kp = kf*8+tg; k padded 35->48
    for (int j = i; j < 12 * 64; j += stride) {
        int row = j >> 6, nb = j & 63;
        int kf = row >> 2, tg = row & 3;
        int kp = kf * 8 + tg;
        int ka = 2 * kp, kb = 2 * kp + 1;
        float a0 = (ka < K1) ? W1[ka * 64 + nb] : 0.f;
        float a1 = (kb < K1) ? W1[kb * 64 + nb] : 0.f;
        int kc = 2 * (kp + 4), kd = 2 * (kp + 4) + 1;
        float c0 = (kc < K1) ? W1[kc * 64 + nb] : 0.f;
        float c1 = (kd < K1) ? W1[kd * 64 + nb] : 0.f;
        g_W1p[j] = make_uint2(pack_f16(a0, a1), pack_f16(c0, c1));
    }
    for (int j = i; j < 16 * 64; j += stride) {
        int row = j >> 6, nb = j & 63;
        int kf = row >> 2, tg = row & 3;
        int kp = kf * 8 + tg;
        g_W2p[j] = make_uint2(
            pack_f16(W2[(2 * kp) * 64 + nb],       W2[(2 * kp + 1) * 64 + nb]),
            pack_f16(W2[(2 * (kp + 4)) * 64 + nb], W2[(2 * (kp + 4) + 1) * 64 + nb]));
    }
    // per-point activation split -> one 128B block per point
    unsigned* fiw = (unsigned*)g_fi;
    int nw = N * 16;
    for (int j = i; j < nw; j += stride) {
        int n = j >> 4, kp = j & 15;
        float2 f = *(const float2*)&point_feat[n * 32 + 2 * kp];
        unsigned hi, lo;
        split_f16(f.x, f.y, hi, lo);
        fiw[(size_t)n * 32 + kp] = hi;
        fiw[(size_t)n * 32 + 16 + kp] = lo;
    }
    for (int j = i; j < E; j += stride)
        atomicAdd(&g_cnt[e_new[j]], 1);
}

// ---------------------------------------------------------------------------
// 2) decoupled-lookback exclusive scan (123 blocks, single wave)
// ---------------------------------------------------------------------------
__global__ void k_scan(int M) {
    __shared__ int sh[SCAN_BLK];
    __shared__ int s_prefix;
    int bid = blockIdx.x;
    int tid = threadIdx.x;
    int i = bid * SCAN_BLK + tid;
    int c = (i < M) ? g_cnt[i] : 0;
    sh[tid] = c;
    __syncthreads();
    for (int d = 1; d < SCAN_BLK; d <<= 1) {
        int t = (tid >= d) ? sh[tid - d] : 0;
        __syncthreads();
        sh[tid] += t;
        __syncthreads();
    }
    int incl = sh[tid];
    if (tid == 0) {
        unsigned agg = (unsigned)sh[SCAN_BLK - 1];
        if (bid == 0) {
            atomicExch(&g_state[0], (2u << 30) | agg);
            s_prefix = 0;
        } else {
            atomicExch(&g_state[bid], (1u << 30) | agg);
            unsigned run = 0;
            int j = bid - 1;
            while (true) {
                unsigned s;
                do { s = atomicAdd(&g_state[j], 0u); } while ((s >> 30) == 0u);
                run += s & 0x3fffffffu;
                if ((s >> 30) == 2u) break;
                j--;
            }
            atomicExch(&g_state[bid], (2u << 30) | (run + agg));
            s_prefix = (int)run;
        }
    }
    __syncthreads();
    if (i < M) g_start[i] = s_prefix + incl - c;
}

// ---------------------------------------------------------------------------
// 3) counting-sort scatter
// ---------------------------------------------------------------------------
__global__ void k_scatter(const int* __restrict__ e_point,
                          const int* __restrict__ e_new, int E) {
    int i = blockIdx.x * blockDim.x + threadIdx.x;
    if (i < E) {
        int m = e_new[i];
        int pos = g_start[m] + atomicAdd(&g_cursor[m], 1);
        g_sorted[pos] = make_int2(e_point[i], m);
    }
}

// ---------------------------------------------------------------------------
__device__ __forceinline__ void mma_f16(float& c0, float& c1, float& c2, float& c3,
                                        unsigned a0, unsigned a1, unsigned a2, unsigned a3,
                                        unsigned b0, unsigned b1) {
    asm volatile("mma.sync.aligned.m16n8k16.row.col.f32.f16.f16.f32 "
                 "{%0,%1,%2,%3}, {%4,%5,%6,%7}, {%8,%9}, {%0,%1,%2,%3};"
                 : "+f"(c0), "+f"(c1), "+f"(c2), "+f"(c3)
                 : "r"(a0), "r"(a1), "r"(a2), "r"(a3), "r"(b0), "r"(b1));
}

// SMEM layout (32-bit word offsets).
// Weight pairs: uint2, row stride 68 (uint2 units) -> conflict-free LDS.64.
// EF row (68 words): [0..16) hi feat, [16..24) hi rel+pad, [24..40) lo feat,
// [40..48) lo rel+pad; layer-2 output overwrites [0..64).
#define S_W1   0                           // uint2 [12][68] -> 1632 words
#define S_W2   1632                        // uint2 [16][68] -> 2176 words
#define S_B1   3808
#define S_B2   (S_B1 + 64)
#define S_MM   (S_B2 + 64)                 // [128] int
#define S_P    (S_MM + 128)                // [128] int (point index per row)
#define S_SC   (S_P + 128)                 // [128][68] words
#define SMEM_WORDS (S_SC + 128 * 68)       // 12832 words = 51328 B -> 4 blocks/SM

// ---------------------------------------------------------------------------
// 4) main tensor-core kernel: 256 threads (8 warps), 128-edge tiles.
//    All staging is warp-local (rows 16w..16w+15 staged by warp w).
// ---------------------------------------------------------------------------
__global__ __launch_bounds__(THREADS, 4)
void k_main_tc(const float4* __restrict__ bxyz4,
               const float*  __restrict__ b1, const float* __restrict__ b2,
               const float4* __restrict__ newb4,
               int*          __restrict__ outf,
               int E, int M)
{
    extern __shared__ float sm[];
    uint2* W1ps = (uint2*)(sm + S_W1);
    uint2* W2ps = (uint2*)(sm + S_W2);
    float* b1s = sm + S_B1;
    float* b2s = sm + S_B2;
    int*   smm = (int*)(sm + S_MM);
    int*   s_p = (int*)(sm + S_P);
    float* sc  = sm + S_SC;
    unsigned* scu = (unsigned*)sm + S_SC;

    int tid  = threadIdx.x;
    int warp = tid >> 5;
    int lane = tid & 31;
    int g    = lane >> 2;
    int tg   = lane & 3;

    // ---- replay-state zeroing (grid*256 covers M) ----
    {
        int gt = blockIdx.x * THREADS + tid;
        if (gt < M) { g_cnt[gt] = 0; g_cursor[gt] = 0; }
        if (gt < 128) g_state[gt] = 0u;
    }

    // ---- stage weight pairs (once per block) ----
    for (int i = tid; i < 12 * 64; i += THREADS) {
        int row = i >> 6, nb = i & 63;
        W1ps[row * 68 + nb] = g_W1p[i];
    }
    for (int i = tid; i < 16 * 64; i += THREADS) {
        int row = i >> 6, nb = i & 63;
        W2ps[row * 68 + nb] = g_W2p[i];
    }
    if (tid < 64) { b1s[tid] = b1[tid]; b2s[tid] = b2[tid]; }

    for (int tb = 0; tb < TPB; tb++) {
        int base = (blockIdx.x * TPB + tb) * TILE;
        if (base >= E) break;
        __syncthreads();    // prior epilogue done before smem tile reuse

        // ---- staging, fully warp-local (warp w owns rows 16w..16w+15) ----
        // step A: even lanes (one per row) write indices + rel-pos split
        {
            int r = warp * 16 + (lane >> 1);
            if ((lane & 1) == 0) {
                int e = base + r;
                unsigned* rp = scu + r * 68;
                if (e < E) {
                    int2 em = g_sorted[e];
                    s_p[r] = em.x;
                    smm[r] = em.y;
                    float4 pb = bxyz4[em.x];
                    float4 nb = newb4[em.y];
                    unsigned h0, l0, h1, l1;
                    split_f16(pb.y - nb.y, pb.z - nb.z, h0, l0);   // (rx, ry)
                    split_f16(pb.w - nb.w, 0.f, h1, l1);           // (rz, 0)
                    ((uint4*)rp)[4]  = make_uint4(h0, h1, 0u, 0u); // hi kp16..19
                    ((uint4*)rp)[5]  = make_uint4(0u, 0u, 0u, 0u); // hi kp20..23
                    ((uint4*)rp)[10] = make_uint4(l0, l1, 0u, 0u); // lo kp16..19
                    ((uint4*)rp)[11] = make_uint4(0u, 0u, 0u, 0u); // lo kp20..23
                } else {
                    s_p[r] = -1;
                    smm[r] = -1;
                    ((uint4*)rp)[4]  = make_uint4(0u, 0u, 0u, 0u);
                    ((uint4*)rp)[5]  = make_uint4(0u, 0u, 0u, 0u);
                    ((uint4*)rp)[10] = make_uint4(0u, 0u, 0u, 0u);
                    ((uint4*)rp)[11] = make_uint4(0u, 0u, 0u, 0u);
                }
            }
        }
        __syncwarp();

        // step B: cooperative feature gather — 8 lanes fetch one point's 128B
        // block (warp instruction touches 4 lines), 4 rows per iteration.
        {
            int q = lane & 7;               // uint4 index within point block
            int ro = lane >> 3;             // row offset within group of 4
            #pragma unroll
            for (int it = 0; it < 4; it++) {
                int r = warp * 16 + it * 4 + ro;
                int p = s_p[r];
                uint4 v = (p >= 0) ? g_fi[(size_t)p * 8 + q]
                                   : make_uint4(0u, 0u, 0u, 0u);
                // dst: hi feat at words [0..16), lo feat at [24..40)
                int dw = (q < 4) ? q * 4 : q * 4 + 8;
                *(uint4*)(scu + r * 68 + dw) = v;
            }
        }
        __syncwarp();       // gathered rows are the rows this warp computes

        int ra = warp * 16 + g;

        // ===== Layer 1, kf-outer, persistent accumulator bank; A=2 terms, B=1 =====
        float acc[8][4];
        #pragma unroll
        for (int nt = 0; nt < 8; nt++) {
            acc[nt][0] = 0.f; acc[nt][1] = 0.f; acc[nt][2] = 0.f; acc[nt][3] = 0.f;
        }
        #pragma unroll
        for (int kf = 0; kf < 3; kf++) {
            int kp = kf * 8 + tg;
            unsigned ah0 = scu[ra * 68 + kp];
            unsigned ah1 = scu[(ra + 8) * 68 + kp];
            unsigned ah2 = scu[ra * 68 + kp + 4];
            unsigned ah3 = scu[(ra + 8) * 68 + kp + 4];
            unsigned al0 = scu[ra * 68 + 24 + kp];
            unsigned al1 = scu[(ra + 8) * 68 + 24 + kp];
            unsigned al2 = scu[ra * 68 + 24 + kp + 4];
            unsigned al3 = scu[(ra + 8) * 68 + 24 + kp + 4];
            int wrow = kf * 4 + tg;
            #pragma unroll
            for (int nt = 0; nt < 8; nt++) {
                int nb = nt * 8 + g;
                uint2 w = W1ps[wrow * 68 + nb];
                mma_f16(acc[nt][0], acc[nt][1], acc[nt][2], acc[nt][3], ah0, ah1, ah2, ah3, w.x, w.y);
                mma_f16(acc[nt][0], acc[nt][1], acc[nt][2], acc[nt][3], al0, al1, al2, al3, w.x, w.y);
            }
        }

        // ---- bias + relu + split: acc bank morphs into layer-2 A bank ----
        unsigned a2h[4][4], a2l[4][4];
        #pragma unroll
        for (int nt = 0; nt < 8; nt++) {
            int col = nt * 8 + 2 * tg;
            float v0 = fmaxf(acc[nt][0] + b1s[col], 0.f);
            float v1 = fmaxf(acc[nt][1] + b1s[col + 1], 0.f);
            float v2 = fmaxf(acc[nt][2] + b1s[col], 0.f);
            float v3 = fmaxf(acc[nt][3] + b1s[col + 1], 0.f);
            // C-frag (rows g/g+8, cols 8nt+2tg) == layer-2 A-frag kf2=nt>>1
            int kf2 = nt >> 1;
            int ix  = (nt & 1) * 2;
            split_f16(v0, v1, a2h[kf2][ix],     a2l[kf2][ix]);
            split_f16(v2, v3, a2h[kf2][ix + 1], a2l[kf2][ix + 1]);
        }

        // ===== Layer 2, nt-outer; A=2 terms, B=1; out -> sc rows (overlays EF) =====
        #pragma unroll
        for (int nt = 0; nt < 8; nt++) {
            float c0 = 0.f, c1 = 0.f, c2 = 0.f, c3 = 0.f;
            int nb = nt * 8 + g;
            #pragma unroll
            for (int kf = 0; kf < 4; kf++) {
                uint2 w = W2ps[(kf * 4 + tg) * 68 + nb];
                mma_f16(c0, c1, c2, c3, a2h[kf][0], a2h[kf][1], a2h[kf][2], a2h[kf][3], w.x, w.y);
                mma_f16(c0, c1, c2, c3, a2l[kf][0], a2l[kf][1], a2l[kf][2], a2l[kf][3], w.x, w.y);
            }
            int col = nt * 8 + 2 * tg;
            *(float2*)&sc[ra * 68 + col] =
                make_float2(fmaxf(c0 + b2s[col], 0.f), fmaxf(c1 + b2s[col + 1], 0.f));
            *(float2*)&sc[(ra + 8) * 68 + col] =
                make_float2(fmaxf(c2 + b2s[col], 0.f), fmaxf(c3 + b2s[col + 1], 0.f));
        }
        __syncthreads();

        // ---- segment-max over the sorted 128-row tile (4 groups x 32 rows) ----
        {
            int c  = tid & 63;
            int rs = (tid >> 6) * 32;
            float best = 0.f;
            int cur = -1;
            #pragma unroll 8
            for (int r = rs; r < rs + 32; r++) {
                int m = smm[r];
                float v = sc[r * 68 + c];
                if (m != cur) {
                    if (cur >= 0)
                        atomicMax(&outf[(size_t)cur * 64 + c], __float_as_int(best));
                    cur = m;
                    best = 0.f;
                }
                best = fmaxf(best, v);    // cur==-1 rows accumulate but never flush
            }
            if (cur >= 0)
                atomicMax(&outf[(size_t)cur * 64 + c], __float_as_int(best));
        }
    }
}

// ---------------------------------------------------------------------------
extern "C" void kernel_launch(void* const* d_in, const int* in_sizes, int n_in,
                              void* d_out, int out_size)
{
    const float* point_bxyz = (const float*)d_in[0];
    const float* point_feat = (const float*)d_in[1];
    const int*   sample_idx = (const int*)  d_in[2];
    const int*   e_point    = (const int*)  d_in[3];
    const int*   e_new      = (const int*)  d_in[4];
    const float* W1         = (const float*)d_in[5];
    const float* b1         = (const float*)d_in[6];
    const float* W2         = (const float*)d_in[7];
    const float* b2         = (const float*)d_in[8];

    float* out = (float*)d_out;
    int N = in_sizes[0] / 4;
    int M = in_sizes[2];
    int E = in_sizes[3];

    cudaFuncSetAttribute(k_main_tc, cudaFuncAttributeMaxDynamicSharedMemorySize,
                         SMEM_WORDS * (int)sizeof(float));

    k_init_hist<<<2048, 256>>>((const float4*)point_bxyz, sample_idx, e_new,
                               point_feat, W1, W2, out, N, M, E);

    int NB = (M + SCAN_BLK - 1) / SCAN_BLK;
    k_scan<<<NB, SCAN_BLK>>>(M);

    k_scatter<<<(E + 255) / 256, 256>>>(e_point, e_new, E);

    int nblk = (E + TILE * TPB - 1) / (TILE * TPB);
    k_main_tc<<<nblk, THREADS, SMEM_WORDS * sizeof(float)>>>(
        (const float4*)point_bxyz,
        b1, b2,
        (const float4*)out,
        (int*)(out + 4 * (size_t)M),
        E, M);
}